// round 13
// baseline (speedup 1.0000x reference)
#include <cuda_runtime.h>
#include <cuda_fp16.h>
#include <math.h>

#define NN    4096
#define RR    4
#define FINN  128
#define HH    64
#define CC    16
#define LLAY  2
#define TT    512
#define ELL_S 128   // max nnz/row (mean ~21.5, sigma ~4.5 -> huge margin)
#define NH    (NN*HH)

// ---- static scratch ----
// RACE INVARIANT: gather kernels must never write the buffer they gather from.
// g_Yh  : written by k_xw1, gathered by k_gcn2.
// g_Y2h : written by k_gcn2, gathered by k_spmm_xhat.
// plane buffers (fp16): ping-pong across k_mrgco layers.
// All fp16 storage is gather-operand-only; accumulation is fp32 throughout.
__device__ float g_d    [RR*NN];                      // D^-1/2 per (relation,row)
__device__ int   g_cnt  [RR*NN];                      // nnz per row
__device__ int   g_cols [RR*NN*ELL_S];                // ELL column indices
__device__ float g_dw   [RR*NN*ELL_S];                // d_j per slot (MRGCO only)
__device__ __align__(16) __half2 g_Yh [RR*NN*32];     // X@W1, pre-scaled by d_j (fp16)
__device__ __align__(16) __half2 g_Y2h[RR*NN*32];     // relu(agg)@W2, pre-scaled (fp16)
__device__ __align__(16) float g_tX[NN*HH*RR];        // interleaved [i][h][r] (head input)
// fp16 plane buffers: slot f of node i holds (plane0[f], plane2[f]); X1h slot q
// holds (plane1[2q], plane1[2q+1]).
__device__ __align__(16) __half2 g_X02h[2][NN*HH];
__device__ __align__(16) __half2 g_X1h [2][NN*32];
__device__ float g_What[LLAY*3*HH*HH];
__device__ float g_losses[TT];
__device__ float g_yscratch[TT*CC];

// ------------------------------------------------------------------
// K1: single dense pass over A -> ELL pattern + degrees. Warp per row.
// ------------------------------------------------------------------
__global__ void k_build(const float* __restrict__ A) {
    int warp = (blockIdx.x * blockDim.x + threadIdx.x) >> 5;
    int lane = threadIdx.x & 31;
    if (warp >= RR * NN) return;
    int i = warp & (NN - 1);
    const float4* row4 = (const float4*)(A + (size_t)warp * NN);
    int* crow = g_cols + (size_t)warp * ELL_S;
    unsigned bm = (1u << lane) - 1u;
    int cnt = 0;
    #pragma unroll 4
    for (int it = 0; it < NN / 128; it++) {
        float4 v = __ldcs(&row4[it * 32 + lane]);
        int jb = it * 128 + lane * 4;
        bool n0 = (v.x != 0.f) || (jb     == i);
        bool n1 = (v.y != 0.f) || (jb + 1 == i);
        bool n2 = (v.z != 0.f) || (jb + 2 == i);
        bool n3 = (v.w != 0.f) || (jb + 3 == i);
        unsigned m0 = __ballot_sync(0xffffffffu, n0);
        unsigned m1 = __ballot_sync(0xffffffffu, n1);
        unsigned m2 = __ballot_sync(0xffffffffu, n2);
        unsigned m3 = __ballot_sync(0xffffffffu, n3);
        int p = cnt + __popc(m0 & bm) + __popc(m1 & bm) + __popc(m2 & bm) + __popc(m3 & bm);
        if (n0) { if (p < ELL_S) crow[p] = jb;     p++; }
        if (n1) { if (p < ELL_S) crow[p] = jb + 1; p++; }
        if (n2) { if (p < ELL_S) crow[p] = jb + 2; p++; }
        if (n3) { if (p < ELL_S) crow[p] = jb + 3; p++; }
        cnt += __popc(m0) + __popc(m1) + __popc(m2) + __popc(m3);
    }
    if (cnt > ELL_S) cnt = ELL_S;
    if (lane == 0) {
        g_cnt[warp] = cnt;
        g_d[warp] = rsqrtf((float)cnt);   // rowsum == cnt (entries exactly 1.0), cnt>=1
    }
}

// K1b: NO dynamic smem. blocks [0,2048): dw (MRGCO); [2048,2080): What.
__global__ void __launch_bounds__(256) k_prep(const float* __restrict__ W) {
    int b = blockIdx.x;
    if (b < 2048) {
        int row = b * 8 + (threadIdx.x >> 5);
        int lane = threadIdx.x & 31;
        int rbase = row & ~(NN - 1);
        int cnt = g_cnt[row];
        const int* crow = g_cols + (size_t)row * ELL_S;
        float* dwr = g_dw + (size_t)row * ELL_S;
        for (int s = lane; s < cnt; s += 32) dwr[s] = g_d[rbase + crow[s]];
    } else {
        int idx = (b - 2048) * 256 + threadIdx.x;   // < LLAY*HH*HH = 8192
        const float* p = W + (size_t)idx * RR;
        float w0 = p[0], w1 = p[1], w2 = p[2], w3 = p[3];
        int l = idx >> 12, q = idx & 4095;
        float* base = g_What + (size_t)l * 3 * HH * HH;
        base[q]           = w0 + w1 + w2 + w3;
        base[HH*HH + q]   = w0 - w2;
        base[2*HH*HH + q] = w0 - w1 + w2 - w3;
    }
}

// K2: Yh[r,j,:] = half(d_rj * (X[j,:] @ W1[r])).  32 rows/block, grid (128,4).
__global__ void __launch_bounds__(256) k_xw1(const float* __restrict__ X,
                                             const float* __restrict__ W1) {
    extern __shared__ float dsm[];
    float* sW = dsm;                 // FINN*HH = 32KB
    float* sX = dsm + FINN * HH;     // 32*FINN = 16KB
    int r = blockIdx.y, i0 = blockIdx.x * 32, tid = threadIdx.x;
    const float4* wg4 = (const float4*)(W1 + (size_t)r * FINN * HH);
    float4* sW4 = (float4*)sW;
    for (int q = tid; q < FINN * HH / 4; q += 256) sW4[q] = wg4[q];
    const float4* xg4 = (const float4*)(X + (size_t)i0 * FINN);
    float4* sX4 = (float4*)sX;
    for (int q = tid; q < 32 * FINN / 4; q += 256) sX4[q] = xg4[q];
    __syncthreads();
    int h = tid & 63, rg = tid >> 6;
    const float* sXb = sX + rg * 8 * FINN;
    float acc[8];
    #pragma unroll
    for (int rr = 0; rr < 8; rr++) acc[rr] = 0.f;
    for (int f = 0; f < FINN; f += 4) {
        float w0 = sW[f*64+h], w1 = sW[(f+1)*64+h], w2 = sW[(f+2)*64+h], w3 = sW[(f+3)*64+h];
        #pragma unroll
        for (int rr = 0; rr < 8; rr++) {
            float4 x = *(const float4*)&sXb[rr * FINN + f];
            acc[rr] += x.x*w0 + x.y*w1 + x.z*w2 + x.w*w3;
        }
    }
    __half* Yh = (__half*)g_Yh;
    #pragma unroll
    for (int rr = 0; rr < 8; rr++) {
        int gi = (r << 12) + i0 + rg * 8 + rr;
        Yh[(size_t)gi * HH + h] = __float2half_rn(g_d[gi] * acc[rr]);
    }
}

// K3 fused: first GCN aggregation (warp per node, half2 gathers of pre-scaled
// g_Yh, fp32 accum, unroll-8 + tail) + relu + @W2 (fp32), output pre-scaled
// fp16 -> g_Y2h. READS g_Yh, WRITES g_Y2h (race invariant).
__global__ void __launch_bounds__(256) k_gcn2(const float* __restrict__ bias,
                                              const float* __restrict__ W2) {
    __shared__ float sW[HH * HH];    // 16KB: W2[r]
    __shared__ float sH[8][HH];      // relu'd hidden rows (fp32)
    int r = blockIdx.y, i0 = blockIdx.x * 8, tid = threadIdx.x;
    int wid = tid >> 5, lane = tid & 31;
    {
        const float4* wg4 = (const float4*)(W2 + (size_t)r * HH * HH);
        float4* sW4 = (float4*)sW;
        for (int q = tid; q < HH * HH / 4; q += 256) sW4[q] = wg4[q];
    }
    int row = (r << 12) + i0 + wid;
    int cnt = g_cnt[row];
    const int* crow = g_cols + (size_t)row * ELL_S;
    const __half2* Yb = g_Yh + (((size_t)r) << 12) * 32;   // relation base (half2 units)
    float ax = 0.f, ay = 0.f;
    int s = 0;
    for (; s + 8 <= cnt; s += 8) {
        int j[8];
        #pragma unroll
        for (int u = 0; u < 8; u++) j[u] = crow[s + u];
        #pragma unroll
        for (int u = 0; u < 8; u++) {
            float2 f = __half22float2(Yb[(size_t)j[u] * 32 + lane]);
            ax += f.x; ay += f.y;
        }
    }
    for (; s < cnt; s++) {
        float2 f = __half22float2(Yb[(size_t)crow[s] * 32 + lane]);
        ax += f.x; ay += f.y;
    }
    float di = g_d[row];
    sH[wid][2*lane]     = fmaxf(di * ax + bias[r * HH + 2*lane], 0.f);
    sH[wid][2*lane + 1] = fmaxf(di * ay + bias[r * HH + 2*lane + 1], 0.f);
    __syncthreads();
    int h = tid & 63, rg = tid >> 6;
    float a0 = 0.f, a1 = 0.f;
    #pragma unroll 8
    for (int j = 0; j < HH; j++) {
        float w = sW[j * 64 + h];
        a0 += sH[rg][j] * w;
        a1 += sH[rg + 4][j] * w;
    }
    int gb = (r << 12) + i0;
    __half* Y2h = (__half*)g_Y2h;
    Y2h[(size_t)(gb + rg)     * HH + h] = __float2half_rn(g_d[gb + rg]     * a0);
    Y2h[(size_t)(gb + rg + 4) * HH + h] = __float2half_rn(g_d[gb + rg + 4] * a1);
}

// K4: second GCN aggregation over pre-scaled g_Y2h (warp per (node,relation),
// 2 nodes/block, half2 gathers, unroll-8 + tail) + fused fp16 plane packing.
__global__ void __launch_bounds__(256) k_spmm_xhat(const float* __restrict__ bias) {
    __shared__ float2 sh[2][4][32];
    int tid = threadIdx.x;
    int wid = tid >> 5, lane = tid & 31;
    int nl = wid >> 2, r = wid & 3;
    int i = blockIdx.x * 2 + nl;
    int row = (r << 12) + i;
    int cnt = g_cnt[row];
    const int* crow = g_cols + (size_t)row * ELL_S;
    const __half2* Yb = g_Y2h + (((size_t)r) << 12) * 32;  // relation base (half2 units)
    float ax = 0.f, ay = 0.f;
    int s = 0;
    for (; s + 8 <= cnt; s += 8) {
        int j[8];
        #pragma unroll
        for (int u = 0; u < 8; u++) j[u] = crow[s + u];
        #pragma unroll
        for (int u = 0; u < 8; u++) {
            float2 f = __half22float2(Yb[(size_t)j[u] * 32 + lane]);
            ax += f.x; ay += f.y;
        }
    }
    for (; s < cnt; s++) {
        float2 f = __half22float2(Yb[(size_t)crow[s] * 32 + lane]);
        ax += f.x; ay += f.y;
    }
    float di = g_d[row];
    float2 v;
    v.x = fmaxf(di * ax + bias[r * HH + 2 * lane], 0.f);
    v.y = fmaxf(di * ay + bias[r * HH + 2 * lane + 1], 0.f);
    sh[nl][r][lane] = v;
    __syncthreads();
    if (r == 0) {   // warps 0 and 4: fp16 plane epilogue for their node
        float2 x0 = sh[nl][0][lane], x1 = sh[nl][1][lane];
        float2 x2 = sh[nl][2][lane], x3 = sh[nl][3][lane];
        int f0 = 2 * lane, f1 = 2 * lane + 1;
        float p0x = x0.x + x1.x + x2.x + x3.x, p0y = x0.y + x1.y + x2.y + x3.y;
        float p2x = x0.x - x1.x + x2.x - x3.x, p2y = x0.y - x1.y + x2.y - x3.y;
        float p1x = x0.x - x2.x,               p1y = x0.y - x2.y;
        g_X02h[0][(size_t)i * HH + f0] = __floats2half2_rn(p0x, p2x);
        g_X02h[0][(size_t)i * HH + f1] = __floats2half2_rn(p0y, p2y);
        g_X1h [0][(size_t)i * 32 + lane] = __floats2half2_rn(p1x, p1y);
    }
}

// Fused MRGCO layer, 320 threads, fp16 plane gathers (fp32 accumulation).
// Ping-pong [src] -> [src^1] (race invariant).
__global__ void __launch_bounds__(320) k_mrgco(int layer, int write_next, int src) {
    __shared__ float part0[4][HH];
    __shared__ float part2[4][HH];
    __shared__ float part1[2][HH];
    __shared__ float sO[3][HH];
    __shared__ float sD[3][HH];
    int i = blockIdx.x, tid = threadIdx.x;
    const __half2* X02s = g_X02h[src];
    const __half2* X1s  = g_X1h[src];
    if (tid < 256) {
        int r = tid >> 6, f = tid & 63;
        int row = (r << 12) + i;
        int cnt = g_cnt[row];
        const int*   crow = g_cols + (size_t)row * ELL_S;
        const float* dwr  = g_dw   + (size_t)row * ELL_S;
        float a0 = 0.f, a2 = 0.f;
        int ss = 0;
        for (; ss + 8 <= cnt; ss += 8) {
            int j[8]; float w[8];
            #pragma unroll
            for (int u = 0; u < 8; u++) { j[u] = crow[ss+u]; w[u] = dwr[ss+u]; }
            #pragma unroll
            for (int u = 0; u < 8; u++) {
                float2 x = __half22float2(X02s[(size_t)j[u] * HH + f]);
                a0 += w[u] * x.x; a2 += w[u] * x.y;
            }
        }
        for (; ss < cnt; ss++) {
            float2 x = __half22float2(X02s[(size_t)crow[ss] * HH + f]);
            a0 += dwr[ss] * x.x; a2 += dwr[ss] * x.y;
        }
        float di = g_d[row];
        float sgn = (r & 1) ? -1.f : 1.f;            // Mc[2][r]
        part0[r][f] = di * a0;                       // Mc[0][r] = +1
        part2[r][f] = sgn * di * a2;
    } else {
        int t2 = tid - 256;                          // 0..63
        int rr = t2 >> 5, q = t2 & 31;
        int r = rr * 2;                              // relations 0, 2
        int row = (r << 12) + i;
        int cnt = g_cnt[row];
        const int*   crow = g_cols + (size_t)row * ELL_S;
        const float* dwr  = g_dw   + (size_t)row * ELL_S;
        float ax = 0.f, ay = 0.f;
        int ss = 0;
        for (; ss + 8 <= cnt; ss += 8) {
            int j[8]; float w[8];
            #pragma unroll
            for (int u = 0; u < 8; u++) { j[u] = crow[ss+u]; w[u] = dwr[ss+u]; }
            #pragma unroll
            for (int u = 0; u < 8; u++) {
                float2 x = __half22float2(X1s[(size_t)j[u] * 32 + q]);
                ax += w[u] * x.x; ay += w[u] * x.y;
            }
        }
        for (; ss < cnt; ss++) {
            float2 x = __half22float2(X1s[(size_t)crow[ss] * 32 + q]);
            ax += dwr[ss] * x.x; ay += dwr[ss] * x.y;
        }
        float c = (rr ? -1.f : 1.f) * g_d[row];      // Mc[1][0]=+1, Mc[1][2]=-1
        part1[rr][2*q]     = c * ax;
        part1[rr][2*q + 1] = c * ay;
    }
    __syncthreads();
    if (tid < HH) {
        float C0 = part0[0][tid] + part0[1][tid] + part0[2][tid] + part0[3][tid];
        float C2 = part2[0][tid] + part2[1][tid] + part2[2][tid] + part2[3][tid];
        float C1 = part1[0][tid] + part1[1][tid];
        float O0 = 0.25f * (C0 + 2.f*C1 + C2);
        float O1 = 0.25f * (C0 - C2);
        float O2 = 0.25f * (C0 - 2.f*C1 + C2);
        float O3 = O1;
        sO[0][tid] = O0 + O1 + O2 + O3;     // Ohat planes
        sO[1][tid] = O0 - O2;
        sO[2][tid] = O0 - O1 + O2 - O3;
    }
    __syncthreads();
    if (tid < 192) {
        int k = tid >> 6, l = tid & 63;
        const float* wk = g_What + (size_t)layer * 3 * HH * HH + (size_t)k * HH * HH;
        float acc = 0.f;
        #pragma unroll 8
        for (int j = 0; j < HH; j++)
            acc += sO[k][j] * __ldg(&wk[j * HH + l]);
        sD[k][l] = acc;
    }
    __syncthreads();
    if (tid < HH) {
        float D0 = sD[0][tid], D1 = sD[1][tid], D2 = sD[2][tid];
        float v0 = 0.25f * (D0 + 2.f*D1 + D2);
        float v1 = 0.25f * (D0 - D2);
        float v2 = 0.25f * (D0 - 2.f*D1 + D2);
        float v3 = v1;
        v0 = fmaxf(v0, 0.f);  v1 = fmaxf(v1, 0.f);
        v2 = fmaxf(v2, 0.f);  v3 = fmaxf(v3, 0.f);
        float4 tv; tv.x = v0; tv.y = v1; tv.z = v2; tv.w = v3;
        *(float4*)&g_tX[((size_t)i * HH + tid) * RR] = tv;
        if (write_next) {
            int dst = src ^ 1;
            float p0 = v0 + v1 + v2 + v3;
            float p1 = v0 - v2;
            float p2 = v0 - v1 + v2 - v3;
            g_X02h[dst][(size_t)i * HH + tid] = __floats2half2_rn(p0, p2);
            ((__half*)g_X1h[dst])[(size_t)i * HH + tid] = __float2half_rn(p1);
        }
    }
}

// Head: 4 targets per block (grid 128), lin1_w cached in smem.
__global__ void k_head(const int* __restrict__ target_x, const int* __restrict__ target,
                       const float* __restrict__ l1w, const float* __restrict__ l1b,
                       const float* __restrict__ l2w, const float* __restrict__ l2b,
                       float* __restrict__ y_out) {
    extern __shared__ float dsm[];
    float* sw1 = dsm;                // 256*64 = 64KB
    float* sf  = sw1 + 256 * HH;     // 256
    float* sp  = sf + 256;           // 4*64
    float* szz = sp + 256;           // 64
    float* sy  = szz + 64;           // 16
    int tid = threadIdx.x;
    {
        const float4* w4 = (const float4*)l1w;
        float4* s4 = (float4*)sw1;
        for (int q = tid; q < 256 * HH / 4; q += 256) s4[q] = w4[q];
    }
    int h = tid & 63, part = tid >> 6;
    for (int tt = 0; tt < 4; tt++) {
        int t = blockIdx.x * 4 + tt;
        __syncthreads();
        int n = target_x[t];
        sf[tid] = g_tX[(size_t)n * 256 + tid];
        __syncthreads();
        float acc = 0.f;
        #pragma unroll 8
        for (int q = part * 64; q < part * 64 + 64; q++)
            acc += sf[q] * sw1[q * 64 + h];
        sp[part * 64 + h] = acc;
        __syncthreads();
        if (tid < HH) {
            float z = sp[tid] + sp[64 + tid] + sp[128 + tid] + sp[192 + tid] + l1b[tid];
            szz[tid] = fmaxf(z, 0.f);
        }
        __syncthreads();
        if (tid < CC) {
            float yv = l2b[tid];
            #pragma unroll 8
            for (int hh = 0; hh < HH; hh++) yv += szz[hh] * l2w[hh * CC + tid];
            sy[tid] = yv;
            y_out[t * CC + tid] = yv;
        }
        __syncthreads();
        if (tid == 0) {
            float mx = sy[0];
            for (int c = 1; c < CC; c++) mx = fmaxf(mx, sy[c]);
            float se = 0.f;
            for (int c = 0; c < CC; c++) se += expf(sy[c] - mx);
            g_losses[t] = mx + logf(se) - sy[target[t]];
        }
    }
}

__global__ void k_loss_reduce(float* __restrict__ loss_ptr) {
    __shared__ float s[256];
    int tid = threadIdx.x;
    s[tid] = g_losses[tid] + g_losses[tid + 256];
    __syncthreads();
    for (int o = 128; o > 0; o >>= 1) {
        if (tid < o) s[tid] += s[tid + o];
        __syncthreads();
    }
    if (tid == 0) *loss_ptr = s[0] / (float)TT;
}

extern "C" void kernel_launch(void* const* d_in, const int* in_sizes, int n_in,
                              void* d_out, int out_size) {
    const float* A        = (const float*)d_in[0];
    const float* X        = (const float*)d_in[1];
    const int*   target_x = (const int*)  d_in[2];
    const int*   target   = (const int*)  d_in[3];
    const float* gw1      = (const float*)d_in[4];
    const float* gb1      = (const float*)d_in[5];
    const float* gw2      = (const float*)d_in[6];
    const float* gb2      = (const float*)d_in[7];
    const float* mw       = (const float*)d_in[8];
    const float* l1w      = (const float*)d_in[9];
    const float* l1b      = (const float*)d_in[10];
    const float* l2w      = (const float*)d_in[11];
    const float* l2b      = (const float*)d_in[12];

    float* outf = (float*)d_out;
    float* loss_ptr = nullptr;
    float* y_dst;
    if (out_size >= TT * CC + 1)  { loss_ptr = outf; y_dst = outf + 1; }
    else if (out_size >= TT * CC) { y_dst = outf; }
    else {
        loss_ptr = outf;
        void* p = nullptr; cudaGetSymbolAddress(&p, g_yscratch);
        y_dst = (float*)p;
    }

    const int XW1_SMEM  = (FINN * HH + 32 * FINN) * 4;              // 48 KB
    const int HEAD_SMEM = (256 * HH + 256 + 256 + 64 + 16) * 4;     // ~66 KB
    cudaFuncSetAttribute(k_xw1,  cudaFuncAttributeMaxDynamicSharedMemorySize, XW1_SMEM);
    cudaFuncSetAttribute(k_head, cudaFuncAttributeMaxDynamicSharedMemorySize, HEAD_SMEM);

    // 1) sparsity pattern + degrees (single DRAM pass over A)
    k_build<<<RR * NN / 8, 256>>>(A);
    // 2) dw fill (MRGCO) + What transform
    k_prep<<<2048 + 32, 256>>>(mw);
    // 3) X @ W1 pre-scaled, fp16 -> g_Yh
    k_xw1<<<dim3(NN / 32, RR), 256, XW1_SMEM>>>(X, gw1);
    // 4) fused: aggregate(g_Yh)+relu+(@W2), pre-scaled fp16 -> g_Y2h
    k_gcn2<<<dim3(NN / 8, RR), 256>>>(gb1, gw2);
    // 5) second aggregation (g_Y2h) + fp16 plane packing into buffer 0
    k_spmm_xhat<<<NN / 2, 256>>>(gb2);
    // 6) MRGCO layers (fp16 plane gathers, ping-pong buffers)
    for (int l = 0; l < LLAY; l++)
        k_mrgco<<<NN, 320>>>(l, l + 1 < LLAY, l & 1);
    // 7) head + deterministic loss reduction
    k_head<<<TT / 4, 256, HEAD_SMEM>>>(target_x, target, l1w, l1b, l2w, l2b, y_dst);
    if (loss_ptr) k_loss_reduce<<<1, 256>>>(loss_ptr);
}

// round 16
// speedup vs baseline: 1.0062x; 1.0062x over previous
// R16 = R14 minus the fused last-block loss reduction (two container failures
// on R14/R15; the atomic handoff was the only novel construct — de-risked).
#include <cuda_runtime.h>
#include <cuda_fp16.h>
#include <math.h>

#define NN    4096
#define RR    4
#define FINN  128
#define HH    64
#define CC    16
#define LLAY  2
#define TT    512
#define ELL_S 128   // max nnz/row (mean ~21.5, sigma ~4.5 -> huge margin)
#define NH    (NN*HH)

// ---- static scratch ----
// RACE INVARIANT: gather kernels must never write the buffer they gather from.
// g_Yh  : written by k_xw1, gathered by k_gcn2.
// g_Y2h : written by k_gcn2, gathered by k_spmm_xhat.
// plane buffers (fp16): ping-pong across k_mrgco layers.
// fp16 is storage-only; accumulation fp32 throughout.
__device__ float g_d    [RR*NN];                      // D^-1/2 per (relation,row)
__device__ int   g_cnt  [RR*NN];                      // nnz per row
__device__ int   g_cols [RR*NN*ELL_S];                // ELL column indices
__device__ __align__(16) __half2 g_Yh [RR*NN*32];     // X@W1, pre-scaled by d_j (fp16)
__device__ __align__(16) __half2 g_Y2h[RR*NN*32];     // relu(agg)@W2, pre-scaled (fp16)
__device__ __align__(16) float g_tX[NN*HH*RR];        // interleaved [i][h][r] (head input)
__device__ __align__(16) __half2 g_X02h[2][NN*HH];    // (plane0,plane2) per feature
__device__ __align__(16) __half2 g_X1h [2][NN*32];    // plane1 feature pairs
__device__ float g_What[LLAY*3*HH*HH];
__device__ float g_losses[TT];
__device__ float g_yscratch[TT*CC];

// ------------------------------------------------------------------
// K1: blocks [0,2048): dense pass over A -> ELL pattern + degrees (warp/row).
//     blocks [2048,2080): What transform (rides free on the BW-bound kernel).
// ------------------------------------------------------------------
__global__ void k_build(const float* __restrict__ A, const float* __restrict__ W) {
    if (blockIdx.x >= 2048) {
        int idx = (blockIdx.x - 2048) * 256 + threadIdx.x;   // < LLAY*HH*HH = 8192
        const float* p = W + (size_t)idx * RR;
        float w0 = p[0], w1 = p[1], w2 = p[2], w3 = p[3];
        int l = idx >> 12, q = idx & 4095;
        float* base = g_What + (size_t)l * 3 * HH * HH;
        base[q]           = w0 + w1 + w2 + w3;
        base[HH*HH + q]   = w0 - w2;
        base[2*HH*HH + q] = w0 - w1 + w2 - w3;
        return;
    }
    int warp = (blockIdx.x * blockDim.x + threadIdx.x) >> 5;
    int lane = threadIdx.x & 31;
    int i = warp & (NN - 1);
    const float4* row4 = (const float4*)(A + (size_t)warp * NN);
    int* crow = g_cols + (size_t)warp * ELL_S;
    unsigned bm = (1u << lane) - 1u;
    int cnt = 0;
    #pragma unroll 4
    for (int it = 0; it < NN / 128; it++) {
        float4 v = __ldcs(&row4[it * 32 + lane]);
        int jb = it * 128 + lane * 4;
        bool n0 = (v.x != 0.f) || (jb     == i);
        bool n1 = (v.y != 0.f) || (jb + 1 == i);
        bool n2 = (v.z != 0.f) || (jb + 2 == i);
        bool n3 = (v.w != 0.f) || (jb + 3 == i);
        unsigned m0 = __ballot_sync(0xffffffffu, n0);
        unsigned m1 = __ballot_sync(0xffffffffu, n1);
        unsigned m2 = __ballot_sync(0xffffffffu, n2);
        unsigned m3 = __ballot_sync(0xffffffffu, n3);
        int p = cnt + __popc(m0 & bm) + __popc(m1 & bm) + __popc(m2 & bm) + __popc(m3 & bm);
        if (n0) { if (p < ELL_S) crow[p] = jb;     p++; }
        if (n1) { if (p < ELL_S) crow[p] = jb + 1; p++; }
        if (n2) { if (p < ELL_S) crow[p] = jb + 2; p++; }
        if (n3) { if (p < ELL_S) crow[p] = jb + 3; p++; }
        cnt += __popc(m0) + __popc(m1) + __popc(m2) + __popc(m3);
    }
    if (cnt > ELL_S) cnt = ELL_S;
    if (lane == 0) {
        g_cnt[warp] = cnt;
        g_d[warp] = rsqrtf((float)cnt);   // rowsum == cnt (entries exactly 1.0), cnt>=1
    }
}

// K2: Yh[r,j,:] = half(d_rj * (X[j,:] @ W1[r])).  32 rows/block, grid (128,4).
__global__ void __launch_bounds__(256) k_xw1(const float* __restrict__ X,
                                             const float* __restrict__ W1) {
    extern __shared__ float dsm[];
    float* sW = dsm;                 // FINN*HH = 32KB
    float* sX = dsm + FINN * HH;     // 32*FINN = 16KB
    int r = blockIdx.y, i0 = blockIdx.x * 32, tid = threadIdx.x;
    const float4* wg4 = (const float4*)(W1 + (size_t)r * FINN * HH);
    float4* sW4 = (float4*)sW;
    for (int q = tid; q < FINN * HH / 4; q += 256) sW4[q] = wg4[q];
    const float4* xg4 = (const float4*)(X + (size_t)i0 * FINN);
    float4* sX4 = (float4*)sX;
    for (int q = tid; q < 32 * FINN / 4; q += 256) sX4[q] = xg4[q];
    __syncthreads();
    int h = tid & 63, rg = tid >> 6;
    const float* sXb = sX + rg * 8 * FINN;
    float acc[8];
    #pragma unroll
    for (int rr = 0; rr < 8; rr++) acc[rr] = 0.f;
    for (int f = 0; f < FINN; f += 4) {
        float w0 = sW[f*64+h], w1 = sW[(f+1)*64+h], w2 = sW[(f+2)*64+h], w3 = sW[(f+3)*64+h];
        #pragma unroll
        for (int rr = 0; rr < 8; rr++) {
            float4 x = *(const float4*)&sXb[rr * FINN + f];
            acc[rr] += x.x*w0 + x.y*w1 + x.z*w2 + x.w*w3;
        }
    }
    __half* Yh = (__half*)g_Yh;
    #pragma unroll
    for (int rr = 0; rr < 8; rr++) {
        int gi = (r << 12) + i0 + rg * 8 + rr;
        Yh[(size_t)gi * HH + h] = __float2half_rn(g_d[gi] * acc[rr]);
    }
}

// K3 fused: first GCN aggregation (warp per node, half2 gathers of pre-scaled
// g_Yh, fp32 accum) + relu + @W2 (fp32) -> pre-scaled fp16 g_Y2h.
// 16 nodes / 512 threads per block.
__global__ void __launch_bounds__(512) k_gcn2(const float* __restrict__ bias,
                                              const float* __restrict__ W2) {
    __shared__ float sW[HH * HH];    // 16KB: W2[r]
    __shared__ float sH[16][HH];     // relu'd hidden rows (fp32)
    int r = blockIdx.y, i0 = blockIdx.x * 16, tid = threadIdx.x;
    int wid = tid >> 5, lane = tid & 31;
    {
        const float4* wg4 = (const float4*)(W2 + (size_t)r * HH * HH);
        float4* sW4 = (float4*)sW;
        for (int q = tid; q < HH * HH / 4; q += 512) sW4[q] = wg4[q];
    }
    int row = (r << 12) + i0 + wid;
    int cnt = g_cnt[row];
    const int* crow = g_cols + (size_t)row * ELL_S;
    const __half2* Yb = g_Yh + (((size_t)r) << 12) * 32;   // relation base (half2 units)
    float ax = 0.f, ay = 0.f;
    int s = 0;
    for (; s + 8 <= cnt; s += 8) {
        int j[8];
        #pragma unroll
        for (int u = 0; u < 8; u++) j[u] = crow[s + u];
        #pragma unroll
        for (int u = 0; u < 8; u++) {
            float2 f = __half22float2(Yb[(size_t)j[u] * 32 + lane]);
            ax += f.x; ay += f.y;
        }
    }
    for (; s < cnt; s++) {
        float2 f = __half22float2(Yb[(size_t)crow[s] * 32 + lane]);
        ax += f.x; ay += f.y;
    }
    float di = g_d[row];
    sH[wid][2*lane]     = fmaxf(di * ax + bias[r * HH + 2*lane], 0.f);
    sH[wid][2*lane + 1] = fmaxf(di * ay + bias[r * HH + 2*lane + 1], 0.f);
    __syncthreads();
    int h = tid & 63, rg = tid >> 6;   // rg 0..7 -> rows rg and rg+8
    float a0 = 0.f, a1 = 0.f;
    #pragma unroll 8
    for (int j = 0; j < HH; j++) {
        float w = sW[j * 64 + h];
        a0 += sH[rg][j] * w;
        a1 += sH[rg + 8][j] * w;
    }
    int gb = (r << 12) + i0;
    __half* Y2h = (__half*)g_Y2h;
    Y2h[(size_t)(gb + rg)     * HH + h] = __float2half_rn(g_d[gb + rg]     * a0);
    Y2h[(size_t)(gb + rg + 8) * HH + h] = __float2half_rn(g_d[gb + rg + 8] * a1);
}

// K4: second GCN aggregation over g_Y2h (warp per (node,relation), 2 nodes/
// block) + fused fp16 plane packing into buffer 0.
__global__ void __launch_bounds__(256) k_spmm_xhat(const float* __restrict__ bias) {
    __shared__ float2 sh[2][4][32];
    int tid = threadIdx.x;
    int wid = tid >> 5, lane = tid & 31;
    int nl = wid >> 2, r = wid & 3;
    int i = blockIdx.x * 2 + nl;
    int row = (r << 12) + i;
    int cnt = g_cnt[row];
    const int* crow = g_cols + (size_t)row * ELL_S;
    const __half2* Yb = g_Y2h + (((size_t)r) << 12) * 32;  // relation base (half2 units)
    float ax = 0.f, ay = 0.f;
    int s = 0;
    for (; s + 8 <= cnt; s += 8) {
        int j[8];
        #pragma unroll
        for (int u = 0; u < 8; u++) j[u] = crow[s + u];
        #pragma unroll
        for (int u = 0; u < 8; u++) {
            float2 f = __half22float2(Yb[(size_t)j[u] * 32 + lane]);
            ax += f.x; ay += f.y;
        }
    }
    for (; s < cnt; s++) {
        float2 f = __half22float2(Yb[(size_t)crow[s] * 32 + lane]);
        ax += f.x; ay += f.y;
    }
    float di = g_d[row];
    float2 v;
    v.x = fmaxf(di * ax + bias[r * HH + 2 * lane], 0.f);
    v.y = fmaxf(di * ay + bias[r * HH + 2 * lane + 1], 0.f);
    sh[nl][r][lane] = v;
    __syncthreads();
    if (r == 0) {   // warps 0 and 4: fp16 plane epilogue for their node
        float2 x0 = sh[nl][0][lane], x1 = sh[nl][1][lane];
        float2 x2 = sh[nl][2][lane], x3 = sh[nl][3][lane];
        int f0 = 2 * lane, f1 = 2 * lane + 1;
        float p0x = x0.x + x1.x + x2.x + x3.x, p0y = x0.y + x1.y + x2.y + x3.y;
        float p2x = x0.x - x1.x + x2.x - x3.x, p2y = x0.y - x1.y + x2.y - x3.y;
        float p1x = x0.x - x2.x,               p1y = x0.y - x2.y;
        g_X02h[0][(size_t)i * HH + f0] = __floats2half2_rn(p0x, p2x);
        g_X02h[0][(size_t)i * HH + f1] = __floats2half2_rn(p0y, p2y);
        g_X1h [0][(size_t)i * 32 + lane] = __floats2half2_rn(p1x, p1y);
    }
}

// Fused MRGCO layer, 320 threads, fp16 plane gathers (fp32 accumulation).
// Neighbor weights d_j read directly from the hot 64KB g_d table.
// Ping-pong [src] -> [src^1] (race invariant).
__global__ void __launch_bounds__(320) k_mrgco(int layer, int write_next, int src) {
    __shared__ float part0[4][HH];
    __shared__ float part2[4][HH];
    __shared__ float part1[2][HH];
    __shared__ float sO[3][HH];
    __shared__ float sD[3][HH];
    int i = blockIdx.x, tid = threadIdx.x;
    const __half2* X02s = g_X02h[src];
    const __half2* X1s  = g_X1h[src];
    if (tid < 256) {
        int r = tid >> 6, f = tid & 63;
        int row = (r << 12) + i;
        int rbase = r << 12;
        int cnt = g_cnt[row];
        const int* crow = g_cols + (size_t)row * ELL_S;
        float a0 = 0.f, a2 = 0.f;
        int ss = 0;
        for (; ss + 8 <= cnt; ss += 8) {
            int j[8]; float w[8];
            #pragma unroll
            for (int u = 0; u < 8; u++) j[u] = crow[ss+u];
            #pragma unroll
            for (int u = 0; u < 8; u++) w[u] = g_d[rbase + j[u]];
            #pragma unroll
            for (int u = 0; u < 8; u++) {
                float2 x = __half22float2(X02s[(size_t)j[u] * HH + f]);
                a0 += w[u] * x.x; a2 += w[u] * x.y;
            }
        }
        for (; ss < cnt; ss++) {
            int j = crow[ss];
            float w = g_d[rbase + j];
            float2 x = __half22float2(X02s[(size_t)j * HH + f]);
            a0 += w * x.x; a2 += w * x.y;
        }
        float di = g_d[row];
        float sgn = (r & 1) ? -1.f : 1.f;            // Mc[2][r]
        part0[r][f] = di * a0;                       // Mc[0][r] = +1
        part2[r][f] = sgn * di * a2;
    } else {
        int t2 = tid - 256;                          // 0..63
        int rr = t2 >> 5, q = t2 & 31;
        int r = rr * 2;                              // relations 0, 2
        int row = (r << 12) + i;
        int rbase = r << 12;
        int cnt = g_cnt[row];
        const int* crow = g_cols + (size_t)row * ELL_S;
        float ax = 0.f, ay = 0.f;
        int ss = 0;
        for (; ss + 8 <= cnt; ss += 8) {
            int j[8]; float w[8];
            #pragma unroll
            for (int u = 0; u < 8; u++) j[u] = crow[ss+u];
            #pragma unroll
            for (int u = 0; u < 8; u++) w[u] = g_d[rbase + j[u]];
            #pragma unroll
            for (int u = 0; u < 8; u++) {
                float2 x = __half22float2(X1s[(size_t)j[u] * 32 + q]);
                ax += w[u] * x.x; ay += w[u] * x.y;
            }
        }
        for (; ss < cnt; ss++) {
            int j = crow[ss];
            float w = g_d[rbase + j];
            float2 x = __half22float2(X1s[(size_t)j * 32 + q]);
            ax += w * x.x; ay += w * x.y;
        }
        float c = (rr ? -1.f : 1.f) * g_d[row];      // Mc[1][0]=+1, Mc[1][2]=-1
        part1[rr][2*q]     = c * ax;
        part1[rr][2*q + 1] = c * ay;
    }
    __syncthreads();
    if (tid < HH) {
        float C0 = part0[0][tid] + part0[1][tid] + part0[2][tid] + part0[3][tid];
        float C2 = part2[0][tid] + part2[1][tid] + part2[2][tid] + part2[3][tid];
        float C1 = part1[0][tid] + part1[1][tid];
        float O0 = 0.25f * (C0 + 2.f*C1 + C2);
        float O1 = 0.25f * (C0 - C2);
        float O2 = 0.25f * (C0 - 2.f*C1 + C2);
        float O3 = O1;
        sO[0][tid] = O0 + O1 + O2 + O3;     // Ohat planes
        sO[1][tid] = O0 - O2;
        sO[2][tid] = O0 - O1 + O2 - O3;
    }
    __syncthreads();
    if (tid < 192) {
        int k = tid >> 6, l = tid & 63;
        const float* wk = g_What + (size_t)layer * 3 * HH * HH + (size_t)k * HH * HH;
        float acc = 0.f;
        #pragma unroll 8
        for (int j = 0; j < HH; j++)
            acc += sO[k][j] * __ldg(&wk[j * HH + l]);
        sD[k][l] = acc;
    }
    __syncthreads();
    if (tid < HH) {
        float D0 = sD[0][tid], D1 = sD[1][tid], D2 = sD[2][tid];
        float v0 = 0.25f * (D0 + 2.f*D1 + D2);
        float v1 = 0.25f * (D0 - D2);
        float v2 = 0.25f * (D0 - 2.f*D1 + D2);
        float v3 = v1;
        v0 = fmaxf(v0, 0.f);  v1 = fmaxf(v1, 0.f);
        v2 = fmaxf(v2, 0.f);  v3 = fmaxf(v3, 0.f);
        float4 tv; tv.x = v0; tv.y = v1; tv.z = v2; tv.w = v3;
        *(float4*)&g_tX[((size_t)i * HH + tid) * RR] = tv;
        if (write_next) {
            int dst = src ^ 1;
            float p0 = v0 + v1 + v2 + v3;
            float p1 = v0 - v2;
            float p2 = v0 - v1 + v2 - v3;
            g_X02h[dst][(size_t)i * HH + tid] = __floats2half2_rn(p0, p2);
            ((__half*)g_X1h[dst])[(size_t)i * HH + tid] = __float2half_rn(p1);
        }
    }
}

// Head: 4 targets per block (grid 128), lin1_w cached in smem.
__global__ void k_head(const int* __restrict__ target_x, const int* __restrict__ target,
                       const float* __restrict__ l1w, const float* __restrict__ l1b,
                       const float* __restrict__ l2w, const float* __restrict__ l2b,
                       float* __restrict__ y_out) {
    extern __shared__ float dsm[];
    float* sw1 = dsm;                // 256*64 = 64KB
    float* sf  = sw1 + 256 * HH;     // 256
    float* sp  = sf + 256;           // 4*64
    float* szz = sp + 256;           // 64
    float* sy  = szz + 64;           // 16
    int tid = threadIdx.x;
    {
        const float4* w4 = (const float4*)l1w;
        float4* s4 = (float4*)sw1;
        for (int q = tid; q < 256 * HH / 4; q += 256) s4[q] = w4[q];
    }
    int h = tid & 63, part = tid >> 6;
    for (int tt = 0; tt < 4; tt++) {
        int t = blockIdx.x * 4 + tt;
        __syncthreads();
        int n = target_x[t];
        sf[tid] = g_tX[(size_t)n * 256 + tid];
        __syncthreads();
        float acc = 0.f;
        #pragma unroll 8
        for (int q = part * 64; q < part * 64 + 64; q++)
            acc += sf[q] * sw1[q * 64 + h];
        sp[part * 64 + h] = acc;
        __syncthreads();
        if (tid < HH) {
            float z = sp[tid] + sp[64 + tid] + sp[128 + tid] + sp[192 + tid] + l1b[tid];
            szz[tid] = fmaxf(z, 0.f);
        }
        __syncthreads();
        if (tid < CC) {
            float yv = l2b[tid];
            #pragma unroll 8
            for (int hh = 0; hh < HH; hh++) yv += szz[hh] * l2w[hh * CC + tid];
            sy[tid] = yv;
            y_out[t * CC + tid] = yv;
        }
        __syncthreads();
        if (tid == 0) {
            float mx = sy[0];
            for (int c = 1; c < CC; c++) mx = fmaxf(mx, sy[c]);
            float se = 0.f;
            for (int c = 0; c < CC; c++) se += expf(sy[c] - mx);
            g_losses[t] = mx + logf(se) - sy[target[t]];
        }
    }
}

// Deterministic fixed-order tree reduction (separate launch — proven safe).
__global__ void k_loss_reduce(float* __restrict__ loss_ptr) {
    __shared__ float s[256];
    int tid = threadIdx.x;
    s[tid] = g_losses[tid] + g_losses[tid + 256];
    __syncthreads();
    for (int o = 128; o > 0; o >>= 1) {
        if (tid < o) s[tid] += s[tid + o];
        __syncthreads();
    }
    if (tid == 0) *loss_ptr = s[0] / (float)TT;
}

extern "C" void kernel_launch(void* const* d_in, const int* in_sizes, int n_in,
                              void* d_out, int out_size) {
    const float* A        = (const float*)d_in[0];
    const float* X        = (const float*)d_in[1];
    const int*   target_x = (const int*)  d_in[2];
    const int*   target   = (const int*)  d_in[3];
    const float* gw1      = (const float*)d_in[4];
    const float* gb1      = (const float*)d_in[5];
    const float* gw2      = (const float*)d_in[6];
    const float* gb2      = (const float*)d_in[7];
    const float* mw       = (const float*)d_in[8];
    const float* l1w      = (const float*)d_in[9];
    const float* l1b      = (const float*)d_in[10];
    const float* l2w      = (const float*)d_in[11];
    const float* l2b      = (const float*)d_in[12];

    float* outf = (float*)d_out;
    float* loss_ptr = nullptr;
    float* y_dst;
    if (out_size >= TT * CC + 1)  { loss_ptr = outf; y_dst = outf + 1; }
    else if (out_size >= TT * CC) { y_dst = outf; }
    else {
        loss_ptr = outf;
        void* p = nullptr; cudaGetSymbolAddress(&p, g_yscratch);
        y_dst = (float*)p;
    }

    const int XW1_SMEM  = (FINN * HH + 32 * FINN) * 4;              // 48 KB
    const int HEAD_SMEM = (256 * HH + 256 + 256 + 64 + 16) * 4;     // ~66 KB
    cudaFuncSetAttribute(k_xw1,  cudaFuncAttributeMaxDynamicSharedMemorySize, XW1_SMEM);
    cudaFuncSetAttribute(k_head, cudaFuncAttributeMaxDynamicSharedMemorySize, HEAD_SMEM);

    // 1) sparsity pattern + degrees + What transform
    k_build<<<2048 + 32, 256>>>(A, mw);
    // 2) X @ W1 pre-scaled, fp16 -> g_Yh
    k_xw1<<<dim3(NN / 32, RR), 256, XW1_SMEM>>>(X, gw1);
    // 3) fused: aggregate(g_Yh)+relu+(@W2), pre-scaled fp16 -> g_Y2h
    k_gcn2<<<dim3(NN / 16, RR), 512>>>(gb1, gw2);
    // 4) second aggregation (g_Y2h) + fp16 plane packing into buffer 0
    k_spmm_xhat<<<NN / 2, 256>>>(gb2);
    // 5) MRGCO layers (fp16 plane gathers, d_j from hot g_d table)
    for (int l = 0; l < LLAY; l++)
        k_mrgco<<<NN, 320>>>(l, l + 1 < LLAY, l & 1);
    // 6) head + deterministic loss reduction (separate launch)
    k_head<<<TT / 4, 256, HEAD_SMEM>>>(target_x, target, l1w, l1b, l2w, l2b, y_dst);
    if (loss_ptr) k_loss_reduce<<<1, 256>>>(loss_ptr);
}